// round 16
// baseline (speedup 1.0000x reference)
#include <cuda_runtime.h>
#include <math.h>
#include <stdint.h>

#define D_MODEL   1024
#define NUM_HEADS 16
#define HEAD_DIM  64
#define BATCH     2
#define SEQ       2048
#define MROWS     (BATCH*SEQ)   /* 4096 */

// ---------------------------------------------------------------------------
// Scratch (allocation-free: __device__ globals).  All tf32-bit buffers.
// g_Xc / g_Wc[0..2] / g_Q / g_K are stored with the K-dim PAIR PERMUTATION:
// within each 8-dim group, original dims (j, j+4) live at physical (2j, 2j+1).
// g_Wc[3], g_V, g_AO are in natural order.
// ---------------------------------------------------------------------------
__device__ uint32_t g_Xc[MROWS * D_MODEL];
__device__ uint32_t g_Wc[4][D_MODEL * D_MODEL];
__device__ uint32_t g_Q[MROWS * D_MODEL];
__device__ uint32_t g_K[MROWS * D_MODEL];
__device__ uint32_t g_V[MROWS * D_MODEL];
__device__ uint32_t g_AO[MROWS * D_MODEL];
__device__ float2   g_rope[SEQ * 32];

extern __shared__ uint32_t dynsmem[];

// ---------------------------------------------------------------------------
// helpers
// ---------------------------------------------------------------------------
__device__ __forceinline__ uint32_t smem_u32(const void* p) {
    uint32_t a;
    asm("{ .reg .u64 t; cvta.to.shared.u64 t, %1; cvt.u32.u64 %0, t; }" : "=r"(a) : "l"(p));
    return a;
}
__device__ __forceinline__ uint32_t f2tf32(float f) {
    uint32_t r;
    asm("cvt.rna.tf32.f32 %0, %1;" : "=r"(r) : "f"(f));
    return r;
}
__device__ __forceinline__ float ex2(float x) {
    float r;
    asm("ex2.approx.f32 %0, %1;" : "=f"(r) : "f"(x));
    return r;
}
__device__ __forceinline__ void cpasync16(uint32_t s, const void* g) {
    asm volatile("cp.async.cg.shared.global [%0], [%1], 16;" :: "r"(s), "l"(g) : "memory");
}
__device__ __forceinline__ void cp_commit() { asm volatile("cp.async.commit_group;" ::: "memory"); }
__device__ __forceinline__ void cp_wait1()  { asm volatile("cp.async.wait_group 1;" ::: "memory"); }
__device__ __forceinline__ void cp_wait0()  { asm volatile("cp.async.wait_group 0;" ::: "memory"); }
__device__ __forceinline__ void lds2(uint32_t& a, uint32_t& b, uint32_t addr) {
    asm volatile("ld.shared.v2.b32 {%0,%1}, [%2];" : "=r"(a), "=r"(b) : "r"(addr));
}

__device__ __forceinline__ void mma_tf32(float c[4], uint32_t a0, uint32_t a1,
                                         uint32_t a2, uint32_t a3,
                                         uint32_t b0, uint32_t b1) {
    asm volatile(
        "mma.sync.aligned.m16n8k8.row.col.f32.tf32.tf32.f32 "
        "{%0,%1,%2,%3}, {%4,%5,%6,%7}, {%8,%9}, {%0,%1,%2,%3};"
        : "+f"(c[0]), "+f"(c[1]), "+f"(c[2]), "+f"(c[3])
        : "r"(a0), "r"(a1), "r"(a2), "r"(a3), "r"(b0), "r"(b1));
}

// ---------------------------------------------------------------------------
// Pre-convert to tf32 bits.  y=0..3 (X, Wq, Wk, Wv): PAIR-PERMUTED K-dim.
// y=4 (Wo): natural order.
// ---------------------------------------------------------------------------
__global__ void conv_tf32_kernel(const float* __restrict__ X,
                                 const float* __restrict__ Wq,
                                 const float* __restrict__ Wk,
                                 const float* __restrict__ Wv,
                                 const float* __restrict__ Wo)
{
    const int i = blockIdx.x * 256 + threadIdx.x;   // float4 index
    const int y = blockIdx.y;
    const float* src;
    uint32_t* dst;
    int n4;
    if (y == 0)      { src = X;  dst = g_Xc;    n4 = MROWS * D_MODEL / 4; }
    else             { src = (y == 1) ? Wq : (y == 2) ? Wk : (y == 3) ? Wv : Wo;
                       dst = g_Wc[y - 1];       n4 = D_MODEL * D_MODEL / 4; }
    if (i >= n4) return;
    float4 v = *(const float4*)&src[i * 4];
    uint32_t u0 = f2tf32(v.x), u1 = f2tf32(v.y), u2 = f2tf32(v.z), u3 = f2tf32(v.w);
    if (y <= 3) {
        // cols i*4..i*4+3 lie in one 8-group; (col&7) is 0 or 4.
        const int e   = i * 4;
        const int row = e >> 10;
        const int col = e & 1023;
        const int g   = col >> 3;
        const int off = (col & 4) ? 1 : 0;
        uint32_t* b = &dst[row * 1024 + g * 8 + off];
        b[0] = u0; b[2] = u1; b[4] = u2; b[6] = u3;
    } else {
        *(uint4*)&dst[i * 4] = make_uint4(u0, u1, u2, u3);
    }
}

// ---------------------------------------------------------------------------
// RoPE table: g_rope[s*32 + i] = (cos, sin).
// ---------------------------------------------------------------------------
__global__ void rope_tab_kernel(const int* __restrict__ pos)
{
    const int id = blockIdx.x * 256 + threadIdx.x;
    if (id >= SEQ * 32) return;
    const int s = id >> 5;
    const int i = id & 31;
    float inv_freq = (float)exp(-(double)i * (9.210340371976184 / 32.0));
    float ang = (float)pos[s] * inv_freq;
    float sn, cs;
    sincosf(ang, &sn, &cs);
    g_rope[id] = make_float2(cs, sn);
}

// ===========================================================================
// GEMM core A (qkv): 128x128 tile, 256 threads, BK=32, 3-stage, 2 CTAs/SM.
// Operands pair-permuted -> fragment loads are ld.shared.v2.
// Q/K outputs stored with head-local pair permutation (after RoPE); V natural.
// ===========================================================================
#define BK        32
#define GSTR      36
#define NTILES    (D_MODEL / BK)     /* 32 */
#define GA_AB     (128 * GSTR)       /* 4608 u32 */
#define GA_STG    (2 * GA_AB)        /* 9216 u32 */
#define GEMM_SMEM_A (3 * GA_STG * 4) /* 110592 B */

__global__ void __launch_bounds__(256, 2)
qkv_gemm_kernel()
{
    const uint32_t* __restrict__ A = g_Xc;
    const uint32_t* __restrict__ W = g_Wc[blockIdx.z];
    uint32_t* __restrict__ Cu = (blockIdx.z == 0) ? g_Q : (blockIdx.z == 1) ? g_K : g_V;
    const int apply_rope = (blockIdx.z < 2);

    uint32_t* sm = dynsmem;
    const int tid   = threadIdx.x;
    const int lane  = tid & 31;
    const int wid   = tid >> 5;
    const int warpM = wid & 1;
    const int warpN = wid >> 1;
    const int gid   = lane >> 2;
    const int tig   = lane & 3;
    const int m0    = blockIdx.y * 128;
    const int n0    = blockIdx.x * 128;

    const uint32_t smbase = smem_u32(sm);
    const int lrow = tid >> 3;
    const int lc4  = (tid & 7) * 4;

    float acc[4][4][4];
#pragma unroll
    for (int i = 0; i < 4; i++)
#pragma unroll
        for (int j = 0; j < 4; j++)
#pragma unroll
            for (int q = 0; q < 4; q++) acc[i][j][q] = 0.0f;

    auto issue_tile = [&](int t, int s) {
        const int k0 = t * BK;
        const uint32_t abase = smbase + (uint32_t)(s * GA_STG) * 4;
        const uint32_t bbase = abase + (uint32_t)GA_AB * 4;
#pragma unroll
        for (int it = 0; it < 4; it++) {
            const int row = lrow + it * 32;
            cpasync16(abase + (uint32_t)(row * GSTR + lc4) * 4,
                      &A[(size_t)(m0 + row) * D_MODEL + k0 + lc4]);
            cpasync16(bbase + (uint32_t)(row * GSTR + lc4) * 4,
                      &W[(size_t)(n0 + row) * D_MODEL + k0 + lc4]);
        }
        cp_commit();
    };

    issue_tile(0, 0);
    issue_tile(1, 1);

    int s0 = 0, s2 = 2;
    for (int t = 0; t < NTILES; t++) {
        if (t + 1 < NTILES) cp_wait1(); else cp_wait0();
        __syncthreads();
        if (t + 2 < NTILES) issue_tile(t + 2, s2);

        const uint32_t abase = smbase + (uint32_t)(s0 * GA_STG) * 4;
        const uint32_t bbase = abase + (uint32_t)GA_AB * 4;
#pragma unroll
        for (int ks = 0; ks < 4; ks++) {
            const int k0 = ks * 8;
            uint32_t af[4][4], bf[4][2];
#pragma unroll
            for (int mf = 0; mf < 4; mf++) {
                const int ra = warpM * 64 + mf * 16 + gid;
                lds2(af[mf][0], af[mf][2], abase + (uint32_t)(ra * GSTR + k0 + 2 * tig) * 4);
                lds2(af[mf][1], af[mf][3], abase + (uint32_t)((ra + 8) * GSTR + k0 + 2 * tig) * 4);
            }
#pragma unroll
            for (int nf = 0; nf < 4; nf++) {
                const int rb = warpN * 32 + nf * 8 + gid;
                lds2(bf[nf][0], bf[nf][1], bbase + (uint32_t)(rb * GSTR + k0 + 2 * tig) * 4);
            }
#pragma unroll
            for (int mf = 0; mf < 4; mf++)
#pragma unroll
                for (int nf = 0; nf < 4; nf++)
                    mma_tf32(acc[mf][nf], af[mf][0], af[mf][1], af[mf][2], af[mf][3],
                             bf[nf][0], bf[nf][1]);
        }
        s0 = (s0 == 2) ? 0 : s0 + 1;
        s2 = (s2 == 2) ? 0 : s2 + 1;
    }

    // ---- epilogue: optional table-RoPE; Q/K stored pair-permuted ----
#pragma unroll
    for (int mf = 0; mf < 4; mf++) {
        const int r = m0 + warpM * 64 + mf * 16 + gid;
        const int s0r = r & (SEQ - 1);
        const int s8r = (r + 8) & (SEQ - 1);
#pragma unroll
        for (int nf = 0; nf < 4; nf++) {
            const int c = n0 + warpN * 32 + nf * 8 + 2 * tig;
            float x0 = acc[mf][nf][0], x1 = acc[mf][nf][1];
            float x2 = acc[mf][nf][2], x3 = acc[mf][nf][3];
            if (apply_rope) {
                const int i = (warpN & 1) * 16 + nf * 4 + tig;
                float2 cs0 = g_rope[s0r * 32 + i];
                float2 cs8 = g_rope[s8r * 32 + i];
                float t0 = x0 * cs0.x - x1 * cs0.y;
                float t1 = x0 * cs0.y + x1 * cs0.x;
                x0 = t0; x1 = t1;
                t0 = x2 * cs8.x - x3 * cs8.y;
                t1 = x2 * cs8.y + x3 * cs8.x;
                x2 = t0; x3 = t1;
                // permuted scatter: orig (d, d+1) -> physical (col0, col0+2)
                const int col0 = c - 2 * tig + (tig < 2 ? 4 * tig : 4 * tig - 7);
                Cu[(size_t)r * D_MODEL + col0]           = f2tf32(x0);
                Cu[(size_t)r * D_MODEL + col0 + 2]       = f2tf32(x1);
                Cu[(size_t)(r + 8) * D_MODEL + col0]     = f2tf32(x2);
                Cu[(size_t)(r + 8) * D_MODEL + col0 + 2] = f2tf32(x3);
            } else {
                *(uint2*)&Cu[(size_t)r * D_MODEL + c] =
                    make_uint2(f2tf32(x0), f2tf32(x1));
                *(uint2*)&Cu[(size_t)(r + 8) * D_MODEL + c] =
                    make_uint2(f2tf32(x2), f2tf32(x3));
            }
        }
    }
}

// ===========================================================================
// GEMM core B (o_proj): 256x128 tile, 512 threads, BK=32, 3-stage.
// Natural (unpermuted) operands: original scalar fragment loads.
// ===========================================================================
#define GB_A      (256 * GSTR)
#define GB_B      (128 * GSTR)
#define GB_STG    (GB_A + GB_B)
#define GEMM_SMEM_B (3 * GB_STG * 4) /* 165888 B */

__global__ void __launch_bounds__(512, 1)
o_gemm_kernel(float* __restrict__ out)
{
    const uint32_t* __restrict__ A = g_AO;
    const uint32_t* __restrict__ W = g_Wc[3];

    uint32_t* sm = dynsmem;
    const int tid   = threadIdx.x;
    const int lane  = tid & 31;
    const int wid   = tid >> 5;
    const int warpM = wid & 3;
    const int warpN = wid >> 2;
    const int gid   = lane >> 2;
    const int tig   = lane & 3;
    const int m0    = blockIdx.y * 256;
    const int n0    = blockIdx.x * 128;

    const uint32_t smbase = smem_u32(sm);
    const int lrow = tid >> 3;
    const int lc4  = (tid & 7) * 4;

    float acc[4][4][4];
#pragma unroll
    for (int i = 0; i < 4; i++)
#pragma unroll
        for (int j = 0; j < 4; j++)
#pragma unroll
            for (int q = 0; q < 4; q++) acc[i][j][q] = 0.0f;

    auto issue_tile = [&](int t, int s) {
        const int k0 = t * BK;
        const uint32_t abase = smbase + (uint32_t)(s * GB_STG) * 4;
        const uint32_t bbase = abase + (uint32_t)GB_A * 4;
#pragma unroll
        for (int it = 0; it < 4; it++) {
            const int row = lrow + it * 64;
            cpasync16(abase + (uint32_t)(row * GSTR + lc4) * 4,
                      &A[(size_t)(m0 + row) * D_MODEL + k0 + lc4]);
        }
#pragma unroll
        for (int it = 0; it < 2; it++) {
            const int row = lrow + it * 64;
            cpasync16(bbase + (uint32_t)(row * GSTR + lc4) * 4,
                      &W[(size_t)(n0 + row) * D_MODEL + k0 + lc4]);
        }
        cp_commit();
    };

    issue_tile(0, 0);
    issue_tile(1, 1);

    int s0 = 0, s2 = 2;
    for (int t = 0; t < NTILES; t++) {
        if (t + 1 < NTILES) cp_wait1(); else cp_wait0();
        __syncthreads();
        if (t + 2 < NTILES) issue_tile(t + 2, s2);

        const uint32_t* At = sm + s0 * GB_STG;
        const uint32_t* Bt = At + GB_A;
#pragma unroll
        for (int ks = 0; ks < 4; ks++) {
            const int k0 = ks * 8;
            uint32_t af[4][4], bf[4][2];
#pragma unroll
            for (int mf = 0; mf < 4; mf++) {
                const int ra = warpM * 64 + mf * 16 + gid;
                af[mf][0] = At[ra * GSTR + k0 + tig];
                af[mf][1] = At[(ra + 8) * GSTR + k0 + tig];
                af[mf][2] = At[ra * GSTR + k0 + tig + 4];
                af[mf][3] = At[(ra + 8) * GSTR + k0 + tig + 4];
            }
#pragma unroll
            for (int nf = 0; nf < 4; nf++) {
                const int rb = warpN * 32 + nf * 8 + gid;
                bf[nf][0] = Bt[rb * GSTR + k0 + tig];
                bf[nf][1] = Bt[rb * GSTR + k0 + tig + 4];
            }
#pragma unroll
            for (int mf = 0; mf < 4; mf++)
#pragma unroll
                for (int nf = 0; nf < 4; nf++)
                    mma_tf32(acc[mf][nf], af[mf][0], af[mf][1], af[mf][2], af[mf][3],
                             bf[nf][0], bf[nf][1]);
        }
        s0 = (s0 == 2) ? 0 : s0 + 1;
        s2 = (s2 == 2) ? 0 : s2 + 1;
    }

#pragma unroll
    for (int mf = 0; mf < 4; mf++) {
        const int r = m0 + warpM * 64 + mf * 16 + gid;
#pragma unroll
        for (int nf = 0; nf < 4; nf++) {
            const int c = n0 + warpN * 32 + nf * 8 + 2 * tig;
            *(float2*)&out[(size_t)r * D_MODEL + c] =
                make_float2(acc[mf][nf][0], acc[mf][nf][1]);
            *(float2*)&out[(size_t)(r + 8) * D_MODEL + c] =
                make_float2(acc[mf][nf][2], acc[mf][nf][3]);
        }
    }
}

// ---------------------------------------------------------------------------
// Causal flash attention.  Q/K pair-permuted -> Q uint2 global loads,
// K ld.shared.v2 fragments (stride 72: conflict-free 8B access).
// V / P / O untouched.  Static log2-domain softmax.  LPT scheduling.
// ---------------------------------------------------------------------------
#define A_BM   128
#define A_BN   64
#define K_STR  72
#define V_STR  72
#define P_STR  68
#define K_U32  (A_BN * K_STR)                 /* 4608 */
#define V_U32  (A_BN * V_STR)                 /* 4608 */
#define VOFF   (2 * K_U32)
#define PSOFF  (2 * K_U32 + 2 * V_U32)        /* 18432 */
#define ATT_SMEM ((PSOFF + A_BM * P_STR) * 4) /* 108544 B */
#define QSCALE (0.125f * 1.4426950408889634f)

__global__ void __launch_bounds__(256)
attn_mma_kernel()
{
    uint32_t* sm = dynsmem;
    const int tid  = threadIdx.x;
    const int lane = tid & 31;
    const int w    = tid >> 5;
    const int gid  = lane >> 2;
    const int tig  = lane & 3;
    const int bh   = blockIdx.y;
    const int b    = bh >> 4;
    const int h    = bh & 15;
    const int qx   = gridDim.x - 1 - blockIdx.x;   // LPT
    const int m0   = qx * A_BM;

    const uint32_t* __restrict__ Qb = g_Q + (size_t)b * SEQ * D_MODEL + h * HEAD_DIM;
    const uint32_t* __restrict__ Kb = g_K + (size_t)b * SEQ * D_MODEL + h * HEAD_DIM;
    const uint32_t* __restrict__ Vb = g_V + (size_t)b * SEQ * D_MODEL + h * HEAD_DIM;

    const uint32_t smbase = smem_u32(sm);
    uint32_t* Ps = sm + PSOFF;

    auto issue = [&](int ti, int bb) {
        const int kt = ti * A_BN;
        const uint32_t kb = smbase + (uint32_t)(bb * K_U32) * 4;
        const uint32_t vb = smbase + (uint32_t)(VOFF + bb * V_U32) * 4;
#pragma unroll
        for (int it = 0; it < 4; it++) {
            const int id  = tid + it * 256;
            const int row = id >> 4;
            const int c4  = (id & 15) * 4;
            cpasync16(kb + (uint32_t)(row * K_STR + c4) * 4,
                      &Kb[(size_t)(kt + row) * D_MODEL + c4]);
            cpasync16(vb + (uint32_t)(row * V_STR + c4) * 4,
                      &Vb[(size_t)(kt + row) * D_MODEL + c4]);
        }
        cp_commit();
    };

    issue(0, 0);

    const int r0 = m0 + w * 16 + gid;
    const int r1 = r0 + 8;

    // Q fragments (pair-permuted layout: slots (tig, tig+4) adjacent)
    uint32_t qf[8][4];
#pragma unroll
    for (int kc = 0; kc < 8; kc++) {
        uint2 qa = *(const uint2*)&Qb[(size_t)r0 * D_MODEL + kc * 8 + 2 * tig];
        uint2 qc = *(const uint2*)&Qb[(size_t)r1 * D_MODEL + kc * 8 + 2 * tig];
        qf[kc][0] = f2tf32(QSCALE * __uint_as_float(qa.x));
        qf[kc][2] = f2tf32(QSCALE * __uint_as_float(qa.y));
        qf[kc][1] = f2tf32(QSCALE * __uint_as_float(qc.x));
        qf[kc][3] = f2tf32(QSCALE * __uint_as_float(qc.y));
    }

    float oacc[8][4];
#pragma unroll
    for (int nf = 0; nf < 8; nf++)
#pragma unroll
        for (int q = 0; q < 4; q++) oacc[nf][q] = 0.0f;
    float l_a = 0.0f, l_b = 0.0f;

    const int nt = (m0 + A_BM) / A_BN;

    for (int ti = 0; ti < nt; ti++) {
        const int bb = ti & 1;
        const int kt = ti * A_BN;
        cp_wait0();
        __syncthreads();
        if (ti + 1 < nt) issue(ti + 1, bb ^ 1);

        const uint32_t kaddr = smbase + (uint32_t)(bb * K_U32) * 4;
        const uint32_t* Vs = sm + VOFF + bb * V_U32;

        // --- S = Q @ K^T (log2 domain); paired K fragment loads ---
        float sacc[8][4];
#pragma unroll
        for (int nf = 0; nf < 8; nf++)
#pragma unroll
            for (int q = 0; q < 4; q++) sacc[nf][q] = 0.0f;

#pragma unroll
        for (int kc = 0; kc < 8; kc++) {
            uint32_t bf[8][2];
#pragma unroll
            for (int nf = 0; nf < 8; nf++) {
                const int rb = nf * 8 + gid;
                lds2(bf[nf][0], bf[nf][1],
                     kaddr + (uint32_t)(rb * K_STR + kc * 8 + 2 * tig) * 4);
            }
#pragma unroll
            for (int nf = 0; nf < 8; nf++)
                mma_tf32(sacc[nf], qf[kc][0], qf[kc][1], qf[kc][2], qf[kc][3],
                         bf[nf][0], bf[nf][1]);
        }

        // --- causal mask ---
        if (kt + A_BN - 1 > m0) {
#pragma unroll
            for (int nf = 0; nf < 8; nf++) {
                const int c = kt + nf * 8 + 2 * tig;
                if (c > r0)     sacc[nf][0] = -1e30f;
                if (c + 1 > r0) sacc[nf][1] = -1e30f;
                if (c > r1)     sacc[nf][2] = -1e30f;
                if (c + 1 > r1) sacc[nf][3] = -1e30f;
            }
        }

        // --- static softmax numerator ---
#pragma unroll
        for (int nf = 0; nf < 8; nf++) {
            sacc[nf][0] = ex2(sacc[nf][0]);
            sacc[nf][1] = ex2(sacc[nf][1]);
            sacc[nf][2] = ex2(sacc[nf][2]);
            sacc[nf][3] = ex2(sacc[nf][3]);
            l_a += sacc[nf][0] + sacc[nf][1];
            l_b += sacc[nf][2] + sacc[nf][3];
        }

        // --- stage P ---
        const int pr0 = w * 16 + gid;
#pragma unroll
        for (int nf = 0; nf < 8; nf++) {
            const int c = nf * 8 + 2 * tig;
            asm volatile("st.shared.v2.b32 [%0], {%1,%2};"
                :: "r"(smem_u32(&Ps[pr0 * P_STR + c])),
                   "r"(f2tf32(sacc[nf][0])), "r"(f2tf32(sacc[nf][1])) : "memory");
            asm volatile("st.shared.v2.b32 [%0], {%1,%2};"
                :: "r"(smem_u32(&Ps[(pr0 + 8) * P_STR + c])),
                   "r"(f2tf32(sacc[nf][2])), "r"(f2tf32(sacc[nf][3])) : "memory");
        }
        __syncwarp();

        // --- O += P @ V ---
#pragma unroll
        for (int kc = 0; kc < 8; kc++) {
            const uint32_t a0 = Ps[pr0 * P_STR + kc * 8 + tig];
            const uint32_t a1 = Ps[(pr0 + 8) * P_STR + kc * 8 + tig];
            const uint32_t a2 = Ps[pr0 * P_STR + kc * 8 + tig + 4];
            const uint32_t a3 = Ps[(pr0 + 8) * P_STR + kc * 8 + tig + 4];
            uint32_t bf[8][2];
#pragma unroll
            for (int nf = 0; nf < 8; nf++) {
                bf[nf][0] = Vs[(kc * 8 + tig) * V_STR + nf * 8 + gid];
                bf[nf][1] = Vs[(kc * 8 + tig + 4) * V_STR + nf * 8 + gid];
            }
#pragma unroll
            for (int nf = 0; nf < 8; nf++)
                mma_tf32(oacc[nf], a0, a1, a2, a3, bf[nf][0], bf[nf][1]);
        }
    }

    // --- final l reduction ---
    l_a += __shfl_xor_sync(0xFFFFFFFFu, l_a, 1);
    l_a += __shfl_xor_sync(0xFFFFFFFFu, l_a, 2);
    l_b += __shfl_xor_sync(0xFFFFFFFFu, l_b, 1);
    l_b += __shfl_xor_sync(0xFFFFFFFFu, l_b, 2);

    const float ila = 1.0f / l_a;
    const float ilb = 1.0f / l_b;
    uint32_t* oa = g_AO + (size_t)(b * SEQ + r0) * D_MODEL + h * HEAD_DIM;
    uint32_t* ob = g_AO + (size_t)(b * SEQ + r1) * D_MODEL + h * HEAD_DIM;
#pragma unroll
    for (int nf = 0; nf < 8; nf++) {
        const int c = nf * 8 + 2 * tig;
        *(uint2*)&oa[c] = make_uint2(f2tf32(oacc[nf][0] * ila), f2tf32(oacc[nf][1] * ila));
        *(uint2*)&ob[c] = make_uint2(f2tf32(oacc[nf][2] * ilb), f2tf32(oacc[nf][3] * ilb));
    }
}

// ---------------------------------------------------------------------------
// Launch
// ---------------------------------------------------------------------------
extern "C" void kernel_launch(void* const* d_in, const int* in_sizes, int n_in,
                              void* d_out, int out_size)
{
    const float* X   = (const float*)d_in[0];
    const float* Wq  = (const float*)d_in[1];
    const float* Wk  = (const float*)d_in[2];
    const float* Wv  = (const float*)d_in[3];
    const float* Wo  = (const float*)d_in[4];
    const int*   pos = (const int*)d_in[5];
    float* out = (float*)d_out;

    static int attr_set = 0;
    if (!attr_set) {
        cudaFuncSetAttribute(qkv_gemm_kernel,
                             cudaFuncAttributeMaxDynamicSharedMemorySize, GEMM_SMEM_A);
        cudaFuncSetAttribute(o_gemm_kernel,
                             cudaFuncAttributeMaxDynamicSharedMemorySize, GEMM_SMEM_B);
        cudaFuncSetAttribute(attn_mma_kernel,
                             cudaFuncAttributeMaxDynamicSharedMemorySize, ATT_SMEM);
        attr_set = 1;
    }

    // 0) convert (pair-permuted for X/Wq/Wk/Wv) + RoPE table
    dim3 cgrid(MROWS * D_MODEL / 4 / 256, 5);
    conv_tf32_kernel<<<cgrid, 256>>>(X, Wq, Wk, Wv, Wo);
    rope_tab_kernel<<<SEQ * 32 / 256, 256>>>(pos);

    // 1) QKV projections with fused table-RoPE (paired fragment loads)
    dim3 ggrid(D_MODEL / 128, MROWS / 128, 3);
    qkv_gemm_kernel<<<ggrid, 256, GEMM_SMEM_A>>>();

    // 2) causal attention (paired K loads, static softmax, LPT)
    dim3 agrid(SEQ / A_BM, BATCH * NUM_HEADS);
    attn_mma_kernel<<<agrid, 256, ATT_SMEM>>>();

    // 3) output projection
    dim3 ogrid(D_MODEL / 128, MROWS / 256, 1);
    o_gemm_kernel<<<ogrid, 512, GEMM_SMEM_B>>>(out);
}

// round 17
// speedup vs baseline: 1.0776x; 1.0776x over previous
#include <cuda_runtime.h>
#include <math.h>
#include <stdint.h>

#define D_MODEL   1024
#define NUM_HEADS 16
#define HEAD_DIM  64
#define BATCH     2
#define SEQ       2048
#define MROWS     (BATCH*SEQ)   /* 4096 */

// ---------------------------------------------------------------------------
// Scratch (allocation-free).  All tf32-bit buffers.
// g_K is stored PAIR-PERMUTED within each 8-dim group: orig dims (j, j+4)
// live at physical (2j, 2j+1).  Everything else is natural order.
// ---------------------------------------------------------------------------
__device__ uint32_t g_Xc[MROWS * D_MODEL];
__device__ uint32_t g_Wc[4][D_MODEL * D_MODEL];
__device__ uint32_t g_Q[MROWS * D_MODEL];
__device__ uint32_t g_K[MROWS * D_MODEL];          // pair-permuted
__device__ uint32_t g_V[MROWS * D_MODEL];
__device__ uint32_t g_AO[MROWS * D_MODEL];
__device__ float2   g_rope[SEQ * 32];

extern __shared__ uint32_t dynsmem[];

// ---------------------------------------------------------------------------
// helpers
// ---------------------------------------------------------------------------
__device__ __forceinline__ uint32_t smem_u32(const void* p) {
    uint32_t a;
    asm("{ .reg .u64 t; cvta.to.shared.u64 t, %1; cvt.u32.u64 %0, t; }" : "=r"(a) : "l"(p));
    return a;
}
__device__ __forceinline__ uint32_t f2tf32(float f) {
    uint32_t r;
    asm("cvt.rna.tf32.f32 %0, %1;" : "=r"(r) : "f"(f));
    return r;
}
__device__ __forceinline__ float ex2(float x) {
    float r;
    asm("ex2.approx.f32 %0, %1;" : "=f"(r) : "f"(x));
    return r;
}
__device__ __forceinline__ void cpasync16(uint32_t s, const void* g) {
    asm volatile("cp.async.cg.shared.global [%0], [%1], 16;" :: "r"(s), "l"(g) : "memory");
}
__device__ __forceinline__ void cp_commit() { asm volatile("cp.async.commit_group;" ::: "memory"); }
__device__ __forceinline__ void cp_wait1()  { asm volatile("cp.async.wait_group 1;" ::: "memory"); }
__device__ __forceinline__ void cp_wait0()  { asm volatile("cp.async.wait_group 0;" ::: "memory"); }
__device__ __forceinline__ void lds2(uint32_t& a, uint32_t& b, uint32_t addr) {
    asm volatile("ld.shared.v2.b32 {%0,%1}, [%2];" : "=r"(a), "=r"(b) : "r"(addr));
}

__device__ __forceinline__ void mma_tf32(float c[4], uint32_t a0, uint32_t a1,
                                         uint32_t a2, uint32_t a3,
                                         uint32_t b0, uint32_t b1) {
    asm volatile(
        "mma.sync.aligned.m16n8k8.row.col.f32.tf32.tf32.f32 "
        "{%0,%1,%2,%3}, {%4,%5,%6,%7}, {%8,%9}, {%0,%1,%2,%3};"
        : "+f"(c[0]), "+f"(c[1]), "+f"(c[2]), "+f"(c[3])
        : "r"(a0), "r"(a1), "r"(a2), "r"(a3), "r"(b0), "r"(b1));
}

// ---------------------------------------------------------------------------
// Pre-convert X and the four weight matrices to tf32 bits (natural order).
// ---------------------------------------------------------------------------
__global__ void conv_tf32_kernel(const float* __restrict__ X,
                                 const float* __restrict__ Wq,
                                 const float* __restrict__ Wk,
                                 const float* __restrict__ Wv,
                                 const float* __restrict__ Wo)
{
    const int i = blockIdx.x * 256 + threadIdx.x;
    const int y = blockIdx.y;
    const float* src;
    uint32_t* dst;
    int n4;
    if (y == 0)      { src = X;  dst = g_Xc;    n4 = MROWS * D_MODEL / 4; }
    else             { src = (y == 1) ? Wq : (y == 2) ? Wk : (y == 3) ? Wv : Wo;
                       dst = g_Wc[y - 1];       n4 = D_MODEL * D_MODEL / 4; }
    if (i >= n4) return;
    float4 v = *(const float4*)&src[i * 4];
    uint4 u;
    u.x = f2tf32(v.x); u.y = f2tf32(v.y); u.z = f2tf32(v.z); u.w = f2tf32(v.w);
    *(uint4*)&dst[i * 4] = u;
}

// ---------------------------------------------------------------------------
// RoPE table: g_rope[s*32 + i] = (cos, sin).
// ---------------------------------------------------------------------------
__global__ void rope_tab_kernel(const int* __restrict__ pos)
{
    const int id = blockIdx.x * 256 + threadIdx.x;
    if (id >= SEQ * 32) return;
    const int s = id >> 5;
    const int i = id & 31;
    float inv_freq = (float)exp(-(double)i * (9.210340371976184 / 32.0));
    float ang = (float)pos[s] * inv_freq;
    float sn, cs;
    sincosf(ang, &sn, &cs);
    g_rope[id] = make_float2(cs, sn);
}

// ===========================================================================
// GEMM core A (qkv): 128x128 tile, 256 threads, BK=32, 3-stage, 2 CTAs/SM.
// Scalar fragment loads (R12 measured-best).  RoPE from table.
// K output (z==1) stored pair-permuted; Q and V natural.
// ===========================================================================
#define BK        32
#define GSTR      36
#define NTILES    (D_MODEL / BK)     /* 32 */
#define GA_AB     (128 * GSTR)
#define GA_STG    (2 * GA_AB)
#define GEMM_SMEM_A (3 * GA_STG * 4) /* 110592 B */

__global__ void __launch_bounds__(256, 2)
qkv_gemm_kernel()
{
    const uint32_t* __restrict__ A = g_Xc;
    const uint32_t* __restrict__ W = g_Wc[blockIdx.z];
    uint32_t* __restrict__ Cu = (blockIdx.z == 0) ? g_Q : (blockIdx.z == 1) ? g_K : g_V;
    const int apply_rope = (blockIdx.z < 2);
    const int permute_out = (blockIdx.z == 1);

    uint32_t* sm = dynsmem;
    const int tid   = threadIdx.x;
    const int lane  = tid & 31;
    const int wid   = tid >> 5;
    const int warpM = wid & 1;
    const int warpN = wid >> 1;
    const int gid   = lane >> 2;
    const int tig   = lane & 3;
    const int m0    = blockIdx.y * 128;
    const int n0    = blockIdx.x * 128;

    const uint32_t smbase = smem_u32(sm);
    const int lrow = tid >> 3;
    const int lc4  = (tid & 7) * 4;

    float acc[4][4][4];
#pragma unroll
    for (int i = 0; i < 4; i++)
#pragma unroll
        for (int j = 0; j < 4; j++)
#pragma unroll
            for (int q = 0; q < 4; q++) acc[i][j][q] = 0.0f;

    auto issue_tile = [&](int t, int s) {
        const int k0 = t * BK;
        const uint32_t abase = smbase + (uint32_t)(s * GA_STG) * 4;
        const uint32_t bbase = abase + (uint32_t)GA_AB * 4;
#pragma unroll
        for (int it = 0; it < 4; it++) {
            const int row = lrow + it * 32;
            cpasync16(abase + (uint32_t)(row * GSTR + lc4) * 4,
                      &A[(size_t)(m0 + row) * D_MODEL + k0 + lc4]);
            cpasync16(bbase + (uint32_t)(row * GSTR + lc4) * 4,
                      &W[(size_t)(n0 + row) * D_MODEL + k0 + lc4]);
        }
        cp_commit();
    };

    issue_tile(0, 0);
    issue_tile(1, 1);

    int s0 = 0, s2 = 2;
    for (int t = 0; t < NTILES; t++) {
        if (t + 1 < NTILES) cp_wait1(); else cp_wait0();
        __syncthreads();
        if (t + 2 < NTILES) issue_tile(t + 2, s2);

        const uint32_t* At = sm + s0 * GA_STG;
        const uint32_t* Bt = At + GA_AB;
#pragma unroll
        for (int ks = 0; ks < 4; ks++) {
            const int k0 = ks * 8;
            uint32_t af[4][4], bf[4][2];
#pragma unroll
            for (int mf = 0; mf < 4; mf++) {
                const int ra = warpM * 64 + mf * 16 + gid;
                af[mf][0] = At[ra * GSTR + k0 + tig];
                af[mf][1] = At[(ra + 8) * GSTR + k0 + tig];
                af[mf][2] = At[ra * GSTR + k0 + tig + 4];
                af[mf][3] = At[(ra + 8) * GSTR + k0 + tig + 4];
            }
#pragma unroll
            for (int nf = 0; nf < 4; nf++) {
                const int rb = warpN * 32 + nf * 8 + gid;
                bf[nf][0] = Bt[rb * GSTR + k0 + tig];
                bf[nf][1] = Bt[rb * GSTR + k0 + tig + 4];
            }
#pragma unroll
            for (int mf = 0; mf < 4; mf++)
#pragma unroll
                for (int nf = 0; nf < 4; nf++)
                    mma_tf32(acc[mf][nf], af[mf][0], af[mf][1], af[mf][2], af[mf][3],
                             bf[nf][0], bf[nf][1]);
        }
        s0 = (s0 == 2) ? 0 : s0 + 1;
        s2 = (s2 == 2) ? 0 : s2 + 1;
    }

    // ---- epilogue: optional table-RoPE; K stored pair-permuted ----
#pragma unroll
    for (int mf = 0; mf < 4; mf++) {
        const int r = m0 + warpM * 64 + mf * 16 + gid;
        const int s0r = r & (SEQ - 1);
        const int s8r = (r + 8) & (SEQ - 1);
#pragma unroll
        for (int nf = 0; nf < 4; nf++) {
            const int c = n0 + warpN * 32 + nf * 8 + 2 * tig;
            float x0 = acc[mf][nf][0], x1 = acc[mf][nf][1];
            float x2 = acc[mf][nf][2], x3 = acc[mf][nf][3];
            if (apply_rope) {
                const int i = (warpN & 1) * 16 + nf * 4 + tig;
                float2 cs0 = g_rope[s0r * 32 + i];
                float2 cs8 = g_rope[s8r * 32 + i];
                float t0 = x0 * cs0.x - x1 * cs0.y;
                float t1 = x0 * cs0.y + x1 * cs0.x;
                x0 = t0; x1 = t1;
                t0 = x2 * cs8.x - x3 * cs8.y;
                t1 = x2 * cs8.y + x3 * cs8.x;
                x2 = t0; x3 = t1;
            }
            if (permute_out) {
                // orig group-offsets (2tig, 2tig+1) -> physical (col0, col0+2)
                const int col0 = c - 2 * tig + (tig < 2 ? 4 * tig : 4 * tig - 7);
                Cu[(size_t)r * D_MODEL + col0]           = f2tf32(x0);
                Cu[(size_t)r * D_MODEL + col0 + 2]       = f2tf32(x1);
                Cu[(size_t)(r + 8) * D_MODEL + col0]     = f2tf32(x2);
                Cu[(size_t)(r + 8) * D_MODEL + col0 + 2] = f2tf32(x3);
            } else {
                *(uint2*)&Cu[(size_t)r * D_MODEL + c] =
                    make_uint2(f2tf32(x0), f2tf32(x1));
                *(uint2*)&Cu[(size_t)(r + 8) * D_MODEL + c] =
                    make_uint2(f2tf32(x2), f2tf32(x3));
            }
        }
    }
}

// ===========================================================================
// GEMM core B (o_proj): 256x128 tile, 512 threads, BK=32, 3-stage.
// ===========================================================================
#define GB_A      (256 * GSTR)
#define GB_B      (128 * GSTR)
#define GB_STG    (GB_A + GB_B)
#define GEMM_SMEM_B (3 * GB_STG * 4) /* 165888 B */

__global__ void __launch_bounds__(512, 1)
o_gemm_kernel(float* __restrict__ out)
{
    const uint32_t* __restrict__ A = g_AO;
    const uint32_t* __restrict__ W = g_Wc[3];

    uint32_t* sm = dynsmem;
    const int tid   = threadIdx.x;
    const int lane  = tid & 31;
    const int wid   = tid >> 5;
    const int warpM = wid & 3;
    const int warpN = wid >> 2;
    const int gid   = lane >> 2;
    const int tig   = lane & 3;
    const int m0    = blockIdx.y * 256;
    const int n0    = blockIdx.x * 128;

    const uint32_t smbase = smem_u32(sm);
    const int lrow = tid >> 3;
    const int lc4  = (tid & 7) * 4;

    float acc[4][4][4];
#pragma unroll
    for (int i = 0; i < 4; i++)
#pragma unroll
        for (int j = 0; j < 4; j++)
#pragma unroll
            for (int q = 0; q < 4; q++) acc[i][j][q] = 0.0f;

    auto issue_tile = [&](int t, int s) {
        const int k0 = t * BK;
        const uint32_t abase = smbase + (uint32_t)(s * GB_STG) * 4;
        const uint32_t bbase = abase + (uint32_t)GB_A * 4;
#pragma unroll
        for (int it = 0; it < 4; it++) {
            const int row = lrow + it * 64;
            cpasync16(abase + (uint32_t)(row * GSTR + lc4) * 4,
                      &A[(size_t)(m0 + row) * D_MODEL + k0 + lc4]);
        }
#pragma unroll
        for (int it = 0; it < 2; it++) {
            const int row = lrow + it * 64;
            cpasync16(bbase + (uint32_t)(row * GSTR + lc4) * 4,
                      &W[(size_t)(n0 + row) * D_MODEL + k0 + lc4]);
        }
        cp_commit();
    };

    issue_tile(0, 0);
    issue_tile(1, 1);

    int s0 = 0, s2 = 2;
    for (int t = 0; t < NTILES; t++) {
        if (t + 1 < NTILES) cp_wait1(); else cp_wait0();
        __syncthreads();
        if (t + 2 < NTILES) issue_tile(t + 2, s2);

        const uint32_t* At = sm + s0 * GB_STG;
        const uint32_t* Bt = At + GB_A;
#pragma unroll
        for (int ks = 0; ks < 4; ks++) {
            const int k0 = ks * 8;
            uint32_t af[4][4], bf[4][2];
#pragma unroll
            for (int mf = 0; mf < 4; mf++) {
                const int ra = warpM * 64 + mf * 16 + gid;
                af[mf][0] = At[ra * GSTR + k0 + tig];
                af[mf][1] = At[(ra + 8) * GSTR + k0 + tig];
                af[mf][2] = At[ra * GSTR + k0 + tig + 4];
                af[mf][3] = At[(ra + 8) * GSTR + k0 + tig + 4];
            }
#pragma unroll
            for (int nf = 0; nf < 4; nf++) {
                const int rb = warpN * 32 + nf * 8 + gid;
                bf[nf][0] = Bt[rb * GSTR + k0 + tig];
                bf[nf][1] = Bt[rb * GSTR + k0 + tig + 4];
            }
#pragma unroll
            for (int mf = 0; mf < 4; mf++)
#pragma unroll
                for (int nf = 0; nf < 4; nf++)
                    mma_tf32(acc[mf][nf], af[mf][0], af[mf][1], af[mf][2], af[mf][3],
                             bf[nf][0], bf[nf][1]);
        }
        s0 = (s0 == 2) ? 0 : s0 + 1;
        s2 = (s2 == 2) ? 0 : s2 + 1;
    }

#pragma unroll
    for (int mf = 0; mf < 4; mf++) {
        const int r = m0 + warpM * 64 + mf * 16 + gid;
#pragma unroll
        for (int nf = 0; nf < 4; nf++) {
            const int c = n0 + warpN * 32 + nf * 8 + 2 * tig;
            *(float2*)&out[(size_t)r * D_MODEL + c] =
                make_float2(acc[mf][nf][0], acc[mf][nf][1]);
            *(float2*)&out[(size_t)(r + 8) * D_MODEL + c] =
                make_float2(acc[mf][nf][2], acc[mf][nf][3]);
        }
    }
}

// ---------------------------------------------------------------------------
// Causal flash attention.  K pair-permuted in gmem -> ld.shared.v2 fragments
// (K_STR=72, conflict-free 8B).  Q natural (scalar LDG prologue).
// Static log2-domain softmax.  LPT scheduling.
// ---------------------------------------------------------------------------
#define A_BM   128
#define A_BN   64
#define K_STR  72
#define V_STR  72
#define P_STR  68
#define K_U32  (A_BN * K_STR)                 /* 4608 */
#define V_U32  (A_BN * V_STR)                 /* 4608 */
#define VOFF   (2 * K_U32)
#define PSOFF  (2 * K_U32 + 2 * V_U32)        /* 18432 */
#define ATT_SMEM ((PSOFF + A_BM * P_STR) * 4) /* 108544 B */
#define QSCALE (0.125f * 1.4426950408889634f)

__global__ void __launch_bounds__(256)
attn_mma_kernel()
{
    uint32_t* sm = dynsmem;
    const int tid  = threadIdx.x;
    const int lane = tid & 31;
    const int w    = tid >> 5;
    const int gid  = lane >> 2;
    const int tig  = lane & 3;
    const int bh   = blockIdx.y;
    const int b    = bh >> 4;
    const int h    = bh & 15;
    const int qx   = gridDim.x - 1 - blockIdx.x;   // LPT
    const int m0   = qx * A_BM;

    const uint32_t* __restrict__ Qb = g_Q + (size_t)b * SEQ * D_MODEL + h * HEAD_DIM;
    const uint32_t* __restrict__ Kb = g_K + (size_t)b * SEQ * D_MODEL + h * HEAD_DIM;
    const uint32_t* __restrict__ Vb = g_V + (size_t)b * SEQ * D_MODEL + h * HEAD_DIM;

    const uint32_t smbase = smem_u32(sm);
    uint32_t* Ps = sm + PSOFF;

    auto issue = [&](int ti, int bb) {
        const int kt = ti * A_BN;
        const uint32_t kb = smbase + (uint32_t)(bb * K_U32) * 4;
        const uint32_t vb = smbase + (uint32_t)(VOFF + bb * V_U32) * 4;
#pragma unroll
        for (int it = 0; it < 4; it++) {
            const int id  = tid + it * 256;
            const int row = id >> 4;
            const int c4  = (id & 15) * 4;
            cpasync16(kb + (uint32_t)(row * K_STR + c4) * 4,
                      &Kb[(size_t)(kt + row) * D_MODEL + c4]);
            cpasync16(vb + (uint32_t)(row * V_STR + c4) * 4,
                      &Vb[(size_t)(kt + row) * D_MODEL + c4]);
        }
        cp_commit();
    };

    issue(0, 0);

    const int r0 = m0 + w * 16 + gid;
    const int r1 = r0 + 8;

    // Q fragments from natural layout (slots tig, tig+4), pre-scaled
    uint32_t qf[8][4];
#pragma unroll
    for (int kc = 0; kc < 8; kc++) {
        qf[kc][0] = f2tf32(QSCALE * __uint_as_float(Qb[(size_t)r0 * D_MODEL + kc * 8 + tig]));
        qf[kc][1] = f2tf32(QSCALE * __uint_as_float(Qb[(size_t)r1 * D_MODEL + kc * 8 + tig]));
        qf[kc][2] = f2tf32(QSCALE * __uint_as_float(Qb[(size_t)r0 * D_MODEL + kc * 8 + tig + 4]));
        qf[kc][3] = f2tf32(QSCALE * __uint_as_float(Qb[(size_t)r1 * D_MODEL + kc * 8 + tig + 4]));
    }

    float oacc[8][4];
#pragma unroll
    for (int nf = 0; nf < 8; nf++)
#pragma unroll
        for (int q = 0; q < 4; q++) oacc[nf][q] = 0.0f;
    float l_a = 0.0f, l_b = 0.0f;

    const int nt = (m0 + A_BM) / A_BN;

    for (int ti = 0; ti < nt; ti++) {
        const int bb = ti & 1;
        const int kt = ti * A_BN;
        cp_wait0();
        __syncthreads();
        if (ti + 1 < nt) issue(ti + 1, bb ^ 1);

        const uint32_t kaddr = smbase + (uint32_t)(bb * K_U32) * 4;
        const uint32_t* Vs = sm + VOFF + bb * V_U32;

        // --- S = Q @ K^T (log2 domain); paired K fragment loads ---
        float sacc[8][4];
#pragma unroll
        for (int nf = 0; nf < 8; nf++)
#pragma unroll
            for (int q = 0; q < 4; q++) sacc[nf][q] = 0.0f;

#pragma unroll
        for (int kc = 0; kc < 8; kc++) {
            uint32_t bf[8][2];
#pragma unroll
            for (int nf = 0; nf < 8; nf++) {
                const int rb = nf * 8 + gid;
                lds2(bf[nf][0], bf[nf][1],
                     kaddr + (uint32_t)(rb * K_STR + kc * 8 + 2 * tig) * 4);
            }
#pragma unroll
            for (int nf = 0; nf < 8; nf++)
                mma_tf32(sacc[nf], qf[kc][0], qf[kc][1], qf[kc][2], qf[kc][3],
                         bf[nf][0], bf[nf][1]);
        }

        // --- causal mask ---
        if (kt + A_BN - 1 > m0) {
#pragma unroll
            for (int nf = 0; nf < 8; nf++) {
                const int c = kt + nf * 8 + 2 * tig;
                if (c > r0)     sacc[nf][0] = -1e30f;
                if (c + 1 > r0) sacc[nf][1] = -1e30f;
                if (c > r1)     sacc[nf][2] = -1e30f;
                if (c + 1 > r1) sacc[nf][3] = -1e30f;
            }
        }

        // --- static softmax numerator ---
#pragma unroll
        for (int nf = 0; nf < 8; nf++) {
            sacc[nf][0] = ex2(sacc[nf][0]);
            sacc[nf][1] = ex2(sacc[nf][1]);
            sacc[nf][2] = ex2(sacc[nf][2]);
            sacc[nf][3] = ex2(sacc[nf][3]);
            l_a += sacc[nf][0] + sacc[nf][1];
            l_b += sacc[nf][2] + sacc[nf][3];
        }

        // --- stage P ---
        const int pr0 = w * 16 + gid;
#pragma unroll
        for (int nf = 0; nf < 8; nf++) {
            const int c = nf * 8 + 2 * tig;
            asm volatile("st.shared.v2.b32 [%0], {%1,%2};"
                :: "r"(smem_u32(&Ps[pr0 * P_STR + c])),
                   "r"(f2tf32(sacc[nf][0])), "r"(f2tf32(sacc[nf][1])) : "memory");
            asm volatile("st.shared.v2.b32 [%0], {%1,%2};"
                :: "r"(smem_u32(&Ps[(pr0 + 8) * P_STR + c])),
                   "r"(f2tf32(sacc[nf][2])), "r"(f2tf32(sacc[nf][3])) : "memory");
        }
        __syncwarp();

        // --- O += P @ V ---
#pragma unroll
        for (int kc = 0; kc < 8; kc++) {
            const uint32_t a0 = Ps[pr0 * P_STR + kc * 8 + tig];
            const uint32_t a1 = Ps[(pr0 + 8) * P_STR + kc * 8 + tig];
            const uint32_t a2 = Ps[pr0 * P_STR + kc * 8 + tig + 4];
            const uint32_t a3 = Ps[(pr0 + 8) * P_STR + kc * 8 + tig + 4];
            uint32_t bf[8][2];
#pragma unroll
            for (int nf = 0; nf < 8; nf++) {
                bf[nf][0] = Vs[(kc * 8 + tig) * V_STR + nf * 8 + gid];
                bf[nf][1] = Vs[(kc * 8 + tig + 4) * V_STR + nf * 8 + gid];
            }
#pragma unroll
            for (int nf = 0; nf < 8; nf++)
                mma_tf32(oacc[nf], a0, a1, a2, a3, bf[nf][0], bf[nf][1]);
        }
    }

    // --- final l reduction ---
    l_a += __shfl_xor_sync(0xFFFFFFFFu, l_a, 1);
    l_a += __shfl_xor_sync(0xFFFFFFFFu, l_a, 2);
    l_b += __shfl_xor_sync(0xFFFFFFFFu, l_b, 1);
    l_b += __shfl_xor_sync(0xFFFFFFFFu, l_b, 2);

    const float ila = 1.0f / l_a;
    const float ilb = 1.0f / l_b;
    uint32_t* oa = g_AO + (size_t)(b * SEQ + r0) * D_MODEL + h * HEAD_DIM;
    uint32_t* ob = g_AO + (size_t)(b * SEQ + r1) * D_MODEL + h * HEAD_DIM;
#pragma unroll
    for (int nf = 0; nf < 8; nf++) {
        const int c = nf * 8 + 2 * tig;
        *(uint2*)&oa[c] = make_uint2(f2tf32(oacc[nf][0] * ila), f2tf32(oacc[nf][1] * ila));
        *(uint2*)&ob[c] = make_uint2(f2tf32(oacc[nf][2] * ilb), f2tf32(oacc[nf][3] * ilb));
    }
}

// ---------------------------------------------------------------------------
// Launch
// ---------------------------------------------------------------------------
extern "C" void kernel_launch(void* const* d_in, const int* in_sizes, int n_in,
                              void* d_out, int out_size)
{
    const float* X   = (const float*)d_in[0];
    const float* Wq  = (const float*)d_in[1];
    const float* Wk  = (const float*)d_in[2];
    const float* Wv  = (const float*)d_in[3];
    const float* Wo  = (const float*)d_in[4];
    const int*   pos = (const int*)d_in[5];
    float* out = (float*)d_out;

    static int attr_set = 0;
    if (!attr_set) {
        cudaFuncSetAttribute(qkv_gemm_kernel,
                             cudaFuncAttributeMaxDynamicSharedMemorySize, GEMM_SMEM_A);
        cudaFuncSetAttribute(o_gemm_kernel,
                             cudaFuncAttributeMaxDynamicSharedMemorySize, GEMM_SMEM_B);
        cudaFuncSetAttribute(attn_mma_kernel,
                             cudaFuncAttributeMaxDynamicSharedMemorySize, ATT_SMEM);
        attr_set = 1;
    }

    // 0) convert (natural order) + RoPE table
    dim3 cgrid(MROWS * D_MODEL / 4 / 256, 5);
    conv_tf32_kernel<<<cgrid, 256>>>(X, Wq, Wk, Wv, Wo);
    rope_tab_kernel<<<SEQ * 32 / 256, 256>>>(pos);

    // 1) QKV projections (K stored pair-permuted)
    dim3 ggrid(D_MODEL / 128, MROWS / 128, 3);
    qkv_gemm_kernel<<<ggrid, 256, GEMM_SMEM_A>>>();

    // 2) causal attention (paired K loads, static softmax, LPT)
    dim3 agrid(SEQ / A_BM, BATCH * NUM_HEADS);
    attn_mma_kernel<<<agrid, 256, ATT_SMEM>>>();

    // 3) output projection
    dim3 ogrid(D_MODEL / 128, MROWS / 256, 1);
    o_gemm_kernel<<<ogrid, 512, GEMM_SMEM_B>>>(out);
}